// round 1
// baseline (speedup 1.0000x reference)
#include <cuda_runtime.h>
#include <cstdint>

// DirectionalCurvatureLoss — fused 3x3 stencil + curvature + |diff| mean on GB300.
// Shapes: pred/target [B,1,1024,1024] fp32, B inferred from in_sizes.
// Output: scalar float.

#define Wd 1024
#define Hd 1024
#define ROWS 8          // output rows per thread
#define QW 4            // output pixels per thread along x (float4)
#define TPB (Wd / QW)   // 256 threads: one block row covers full width
#define EPSV 1e-8f

__device__ float g_partials[8192];   // per-block weighted partial sums

__device__ __forceinline__ float f_rcp(float x) {
    float y; asm("rcp.approx.f32 %0, %1;" : "=f"(y) : "f"(x)); return y;
}
__device__ __forceinline__ float f_sqrt(float x) {
    float y; asm("sqrt.approx.f32 %0, %1;" : "=f"(y) : "f"(x)); return y;
}

// Load 6 consecutive values (x0-1 .. x0+4) of row y; zero pad outside image.
__device__ __forceinline__ void load_row(const float* __restrict__ img, int y, int x0,
                                         float out[6]) {
    if ((unsigned)y < (unsigned)Hd) {
        const float* rp = img + (size_t)y * Wd + x0;
        float4 v = *reinterpret_cast<const float4*>(rp);
        out[1] = v.x; out[2] = v.y; out[3] = v.z; out[4] = v.w;
        out[0] = (x0 > 0)        ? rp[-1] : 0.f;
        out[5] = (x0 + 4 < Wd)   ? rp[4]  : 0.f;
    } else {
        #pragma unroll
        for (int i = 0; i < 6; i++) out[i] = 0.f;
    }
}

// Curvatures for 4 pixels from three 6-wide rows (a=y-1, b=y, c=y+1).
// XLA conv = cross-correlation, zero SAME padding.
__device__ __forceinline__ void curv4(const float a[6], const float b[6], const float c[6],
                                      float prof[4], float plan[4], float mn[4]) {
    float v1[6], w[6], cs[6], dd[6];
    #pragma unroll
    for (int i = 0; i < 6; i++) {
        v1[i] = a[i] + c[i];            // top+bottom
        w[i]  = fmaf(2.f, b[i], v1[i]); // vertical 1,2,1
        cs[i] = v1[i] + b[i];           // column sum
        dd[i] = c[i] - a[i];            // bottom-top
    }
    #pragma unroll
    for (int j = 0; j < 4; j++) {
        // p = sobel_x/(8*10), q = sobel_y/(8*10), r = k_xx/(3*100),
        // s = k_xy/(4*100), t = k_yy/(3*100)
        float p  = (w[j+2] - w[j]) * (1.f / 80.f);
        float q  = (dd[j] + 2.f * dd[j+1] + dd[j+2]) * (1.f / 80.f);
        float r  = (cs[j] - 2.f * cs[j+1] + cs[j+2]) * (1.f / 300.f);
        float tt = ((v1[j] + v1[j+1] + v1[j+2]) - 2.f * (b[j] + b[j+1] + b[j+2]))
                   * (1.f / 300.f);
        float s  = ((a[j+2] - a[j]) + (c[j] - c[j+2])) * (1.f / 400.f);

        float p2 = p * p, q2 = q * q, pq = p * q;
        float d  = p2 + q2;
        float onepd = 1.f + d;
        float sq1 = f_sqrt(onepd);
        float sqd = f_sqrt(d);

        float A = fmaf(d, sq1, EPSV);              // denom1*sqrt(1+denom1)+eps
        float B = fmaf(d, sqd, EPSV);              // denom1^1.5 + eps
        float C = fmaf(2.f * onepd, sq1, EPSV);    // 2*(1+denom1)^1.5 + eps

        float AB = A * B;
        float ip = f_rcp(AB * C);                  // one rcp serves all three
        float invA = ip * (B * C);
        float invB = ip * (A * C);
        float invC = ip * AB;

        float rp2 = r * p2, tq2 = tt * q2, rq2 = r * q2, tp2 = tt * p2;
        float s2pq = 2.f * s * pq;
        float n1 = rp2 + s2pq + tq2;
        float n2 = (rq2 - s2pq) + tp2;
        float n3 = (r + tt) + ((rq2 + tp2) - s2pq);

        bool flat = d < EPSV;
        prof[j] = flat ? 0.f : n1 * invA;
        plan[j] = flat ? 0.f : n2 * invB;
        mn[j]   = n3 * invC;
    }
}

__global__ void __launch_bounds__(TPB, 2)
curv_loss_kernel(const float* __restrict__ pred, const float* __restrict__ target) {
    const int x0 = threadIdx.x * QW;
    const int y0 = blockIdx.x * ROWS;
    const size_t img_off = (size_t)blockIdx.y * (size_t)(Hd * Wd);
    const float* P = pred + img_off;
    const float* T = target + img_off;

    float pA[6], pB[6], pC[6], tA[6], tB[6], tC[6];
    load_row(P, y0 - 1, x0, pA);
    load_row(P, y0,     x0, pB);
    load_row(T, y0 - 1, x0, tA);
    load_row(T, y0,     x0, tB);

    float sp = 0.f, sl = 0.f, sm = 0.f;

    #pragma unroll 2
    for (int rr = 0; rr < ROWS; rr++) {
        load_row(P, y0 + rr + 1, x0, pC);
        load_row(T, y0 + rr + 1, x0, tC);

        float prP[4], plP[4], mnP[4], prT[4], plT[4], mnT[4];
        curv4(pA, pB, pC, prP, plP, mnP);
        curv4(tA, tB, tC, prT, plT, mnT);

        #pragma unroll
        for (int j = 0; j < 4; j++) {
            sp += fabsf(prP[j] - prT[j]);
            sl += fabsf(plP[j] - plT[j]);
            sm += fabsf(mnP[j] - mnT[j]);
        }
        #pragma unroll
        for (int i = 0; i < 6; i++) {
            pA[i] = pB[i]; pB[i] = pC[i];
            tA[i] = tB[i]; tB[i] = tC[i];
        }
    }

    // block reduction (deterministic tree)
    #pragma unroll
    for (int off = 16; off > 0; off >>= 1) {
        sp += __shfl_xor_sync(0xFFFFFFFFu, sp, off);
        sl += __shfl_xor_sync(0xFFFFFFFFu, sl, off);
        sm += __shfl_xor_sync(0xFFFFFFFFu, sm, off);
    }
    __shared__ float sh[TPB / 32][3];
    int wid = threadIdx.x >> 5, lid = threadIdx.x & 31;
    if (lid == 0) { sh[wid][0] = sp; sh[wid][1] = sl; sh[wid][2] = sm; }
    __syncthreads();
    if (threadIdx.x == 0) {
        float a = 0.f, b = 0.f, c = 0.f;
        #pragma unroll
        for (int i = 0; i < TPB / 32; i++) { a += sh[i][0]; b += sh[i][1]; c += sh[i][2]; }
        int bid = blockIdx.y * gridDim.x + blockIdx.x;
        g_partials[bid] = 0.5f * a + 0.3f * b + 0.2f * c;
    }
}

__global__ void finalize_kernel(float* __restrict__ out, int nblocks, double invN) {
    __shared__ double sh[256];
    double acc = 0.0;
    for (int i = threadIdx.x; i < nblocks; i += 256)
        acc += (double)g_partials[i];
    sh[threadIdx.x] = acc;
    __syncthreads();
    for (int off = 128; off > 0; off >>= 1) {
        if (threadIdx.x < off) sh[threadIdx.x] += sh[threadIdx.x + off];
        __syncthreads();
    }
    if (threadIdx.x == 0) out[0] = (float)(sh[0] * invN);
}

extern "C" void kernel_launch(void* const* d_in, const int* in_sizes, int n_in,
                              void* d_out, int out_size) {
    const float* pred   = (const float*)d_in[0];
    const float* target = (const float*)d_in[1];
    float* out = (float*)d_out;

    int B = in_sizes[0] / (Hd * Wd);
    if (B < 1) B = 1;

    dim3 grid(Hd / ROWS, B);   // 128 x B blocks
    curv_loss_kernel<<<grid, TPB>>>(pred, target);

    int nblocks = (Hd / ROWS) * B;
    double invN = 1.0 / ((double)B * Hd * Wd);
    finalize_kernel<<<1, 256>>>(out, nblocks, invN);
}

// round 2
// speedup vs baseline: 1.0612x; 1.0612x over previous
#include <cuda_runtime.h>
#include <cstdint>

// DirectionalCurvatureLoss — fused 3x3 stencil + curvature + |diff| mean on GB300.
// pred/target packed lane-wise into f32x2 (Blackwell packed-fp32 pipe).
// Single kernel: last block finishes the reduction (no second launch).

#define Wd 1024
#define Hd 1024
#define ROWS 8
#define QW 4
#define TPB (Wd / QW)   // 256
#define EPSV 1e-8f

typedef unsigned long long u64;

__device__ float g_partials[8192];
__device__ unsigned int g_count;

__device__ __forceinline__ float f_rcp(float x) {
    float y; asm("rcp.approx.f32 %0, %1;" : "=f"(y) : "f"(x)); return y;
}
__device__ __forceinline__ float f_sqrt(float x) {
    float y; asm("sqrt.approx.f32 %0, %1;" : "=f"(y) : "f"(x)); return y;
}

// ── packed f32x2 helpers ────────────────────────────────────────────────
__device__ __forceinline__ u64 pk(float lo, float hi) {
    u64 r; asm("mov.b64 %0, {%1, %2};" : "=l"(r) : "f"(lo), "f"(hi)); return r;
}
__device__ __forceinline__ void unpk(u64 x, float& lo, float& hi) {
    asm("mov.b64 {%0, %1}, %2;" : "=f"(lo), "=f"(hi) : "l"(x));
}
__device__ __forceinline__ u64 fma2(u64 a, u64 b, u64 c) {
    u64 r; asm("fma.rn.f32x2 %0, %1, %2, %3;" : "=l"(r) : "l"(a), "l"(b), "l"(c)); return r;
}
__device__ __forceinline__ u64 add2(u64 a, u64 b) {
    u64 r; asm("add.rn.f32x2 %0, %1, %2;" : "=l"(r) : "l"(a), "l"(b)); return r;
}
__device__ __forceinline__ u64 mul2(u64 a, u64 b) {
    u64 r; asm("mul.rn.f32x2 %0, %1, %2;" : "=l"(r) : "l"(a), "l"(b)); return r;
}

#define PK2(c) pk((c), (c))

// Load 6 consecutive packed (pred,target) values of row y; zero outside image.
__device__ __forceinline__ void load_row2(const float* __restrict__ P,
                                          const float* __restrict__ T,
                                          int y, int x0, u64 out[6]) {
    if ((unsigned)y < (unsigned)Hd) {
        const float* rp = P + (size_t)y * Wd + x0;
        const float* rt = T + (size_t)y * Wd + x0;
        float4 vp = *reinterpret_cast<const float4*>(rp);
        float4 vt = *reinterpret_cast<const float4*>(rt);
        out[1] = pk(vp.x, vt.x); out[2] = pk(vp.y, vt.y);
        out[3] = pk(vp.z, vt.z); out[4] = pk(vp.w, vt.w);
        out[0] = (x0 > 0)      ? pk(rp[-1], rt[-1]) : 0ull;
        out[5] = (x0 + 4 < Wd) ? pk(rp[4],  rt[4])  : 0ull;
    } else {
        #pragma unroll
        for (int i = 0; i < 6; i++) out[i] = 0ull;
    }
}

__global__ void __launch_bounds__(TPB, 2)
curv_loss_kernel(const float* __restrict__ pred, const float* __restrict__ target,
                 int nblocks, double invN, float* __restrict__ out) {
    const int x0 = threadIdx.x * QW;
    const int y0 = blockIdx.x * ROWS;
    const size_t img_off = (size_t)blockIdx.y * (size_t)(Hd * Wd);
    const float* P = pred + img_off;
    const float* T = target + img_off;

    const u64 NEG1 = PK2(-1.f);
    const u64 TWO  = PK2(2.f);
    const u64 M2   = PK2(-2.f);
    const u64 ONE  = PK2(1.f);
    const u64 EPS2 = PK2(EPSV);
    const u64 C80  = PK2(1.f / 80.f);
    const u64 C300 = PK2(1.f / 300.f);
    const u64 C400 = PK2(1.f / 400.f);
    #define SUB2(a, b) fma2((b), NEG1, (a))   // exact a-b

    u64 ra[6], rb[6], rc[6];
    load_row2(P, T, y0 - 1, x0, ra);
    load_row2(P, T, y0,     x0, rb);

    float sp = 0.f, sl = 0.f, sm = 0.f;

    #pragma unroll 2
    for (int rr = 0; rr < ROWS; rr++) {
        load_row2(P, T, y0 + rr + 1, x0, rc);

        u64 v1[6], dd[6];
        #pragma unroll
        for (int i = 0; i < 6; i++) {
            v1[i] = add2(ra[i], rc[i]);   // top+bottom
            dd[i] = SUB2(rc[i], ra[i]);   // bottom-top
        }

        #pragma unroll
        for (int j = 0; j < 4; j++) {
            // packed derivatives: p,q,r,t,s — cross-correlation, zero SAME pad
            u64 p  = mul2(fma2(SUB2(rb[j+2], rb[j]), TWO, SUB2(v1[j+2], v1[j])), C80);
            u64 q  = mul2(add2(fma2(dd[j+1], TWO, dd[j]), dd[j+2]), C80);
            u64 sv = add2(v1[j], v1[j+2]);
            u64 sb = add2(rb[j], rb[j+2]);
            u64 r  = mul2(add2(fma2(v1[j+1], M2, sv), fma2(rb[j+1], M2, sb)), C300);
            u64 tt = mul2(fma2(add2(sb, rb[j+1]), M2, add2(sv, v1[j+1])), C300);
            u64 s  = mul2(add2(SUB2(ra[j+2], ra[j]), SUB2(rc[j], rc[j+2])), C400);

            u64 p2 = mul2(p, p), q2 = mul2(q, q), pq = mul2(p, q);
            u64 d  = add2(p2, q2);
            u64 onepd = add2(d, ONE);

            float dl, dh, ol, oh;
            unpk(d, dl, dh); unpk(onepd, ol, oh);
            u64 sq1 = pk(f_sqrt(ol), f_sqrt(oh));
            u64 sqd = pk(f_sqrt(dl), f_sqrt(dh));

            u64 A = fma2(d, sq1, EPS2);                  // d*sqrt(1+d)+eps
            u64 B = fma2(d, sqd, EPS2);                  // d^1.5+eps
            u64 C = fma2(add2(onepd, onepd), sq1, EPS2); // 2*(1+d)^1.5+eps

            u64 AB  = mul2(A, B);
            u64 ABC = mul2(AB, C);
            float il, ih; unpk(ABC, il, ih);
            u64 ip = pk(f_rcp(il), f_rcp(ih));           // one rcp per half
            u64 invA = mul2(ip, mul2(B, C));
            u64 invB = mul2(ip, mul2(A, C));
            u64 invC = mul2(ip, AB);

            u64 rp2 = mul2(r, p2), tq2 = mul2(tt, q2);
            u64 rq2 = mul2(r, q2), tp2 = mul2(tt, p2);
            u64 s2pq = mul2(add2(s, s), pq);
            u64 prof = mul2(add2(add2(rp2, s2pq), tq2), invA);
            u64 plan = mul2(add2(SUB2(rq2, s2pq), tp2), invB);
            u64 mn   = mul2(add2(add2(r, tt), SUB2(add2(rq2, tp2), s2pq)), invC);

            float a0, a1;
            unpk(prof, a0, a1);
            if (dl < EPSV) a0 = 0.f;
            if (dh < EPSV) a1 = 0.f;
            sp += fabsf(a0 - a1);
            unpk(plan, a0, a1);
            if (dl < EPSV) a0 = 0.f;
            if (dh < EPSV) a1 = 0.f;
            sl += fabsf(a0 - a1);
            unpk(mn, a0, a1);
            sm += fabsf(a0 - a1);
        }

        #pragma unroll
        for (int i = 0; i < 6; i++) { ra[i] = rb[i]; rb[i] = rc[i]; }
    }

    // ── deterministic block reduction ──────────────────────────────────
    #pragma unroll
    for (int off = 16; off > 0; off >>= 1) {
        sp += __shfl_xor_sync(0xFFFFFFFFu, sp, off);
        sl += __shfl_xor_sync(0xFFFFFFFFu, sl, off);
        sm += __shfl_xor_sync(0xFFFFFFFFu, sm, off);
    }
    __shared__ float sh[TPB / 32][3];
    __shared__ bool islast;
    int wid = threadIdx.x >> 5, lid = threadIdx.x & 31;
    if (lid == 0) { sh[wid][0] = sp; sh[wid][1] = sl; sh[wid][2] = sm; }
    __syncthreads();
    if (threadIdx.x == 0) {
        float a = 0.f, b = 0.f, c = 0.f;
        #pragma unroll
        for (int i = 0; i < TPB / 32; i++) { a += sh[i][0]; b += sh[i][1]; c += sh[i][2]; }
        int bid = blockIdx.y * gridDim.x + blockIdx.x;
        g_partials[bid] = 0.5f * a + 0.3f * b + 0.2f * c;
        __threadfence();
        unsigned prev = atomicAdd(&g_count, 1u);
        islast = (prev == (unsigned)(nblocks - 1));
    }
    __syncthreads();

    // ── last block finishes: fixed-order double reduction, reset counter ─
    if (islast) {
        __threadfence();   // acquire all partials
        __shared__ double shd[TPB];
        double acc = 0.0;
        for (int i = threadIdx.x; i < nblocks; i += TPB)
            acc += (double)g_partials[i];
        shd[threadIdx.x] = acc;
        __syncthreads();
        for (int off = TPB / 2; off > 0; off >>= 1) {
            if (threadIdx.x < off) shd[threadIdx.x] += shd[threadIdx.x + off];
            __syncthreads();
        }
        if (threadIdx.x == 0) {
            out[0] = (float)(shd[0] * invN);
            g_count = 0;   // reset for next graph replay
        }
    }
}

extern "C" void kernel_launch(void* const* d_in, const int* in_sizes, int n_in,
                              void* d_out, int out_size) {
    const float* pred   = (const float*)d_in[0];
    const float* target = (const float*)d_in[1];
    float* out = (float*)d_out;

    int B = in_sizes[0] / (Hd * Wd);
    if (B < 1) B = 1;

    dim3 grid(Hd / ROWS, B);           // 128 x B = 2048 blocks
    int nblocks = (Hd / ROWS) * B;
    double invN = 1.0 / ((double)B * Hd * Wd);
    curv_loss_kernel<<<grid, TPB>>>(pred, target, nblocks, invN, out);
}

// round 5
// speedup vs baseline: 1.1763x; 1.1085x over previous
#include <cuda_runtime.h>
#include <cstdint>

// DirectionalCurvatureLoss — fused stencil + curvature + |diff| mean, GB300.
// (pred,target) packed into f32x2; software-pipelined row loads; fused finalize.

#define Wd 1024
#define Hd 1024
#define ROWS 8
#define QW 4
#define TPB 256
#define EPSV 1e-8f

typedef unsigned long long u64;

__device__ float g_partials[8192];
__device__ unsigned int g_count;

__device__ __forceinline__ float f_rcp(float x) {
    float y; asm("rcp.approx.f32 %0, %1;" : "=f"(y) : "f"(x)); return y;
}
__device__ __forceinline__ float f_sqrt(float x) {
    float y; asm("sqrt.approx.f32 %0, %1;" : "=f"(y) : "f"(x)); return y;
}
__device__ __forceinline__ float f_rsqrt(float x) {
    float y; asm("rsqrt.approx.f32 %0, %1;" : "=f"(y) : "f"(x)); return y;
}

__device__ __forceinline__ u64 pk(float lo, float hi) {
    u64 r; asm("mov.b64 %0, {%1, %2};" : "=l"(r) : "f"(lo), "f"(hi)); return r;
}
__device__ __forceinline__ void unpk(u64 x, float& lo, float& hi) {
    asm("mov.b64 {%0, %1}, %2;" : "=f"(lo), "=f"(hi) : "l"(x));
}
__device__ __forceinline__ u64 fma2(u64 a, u64 b, u64 c) {
    u64 r; asm("fma.rn.f32x2 %0, %1, %2, %3;" : "=l"(r) : "l"(a), "l"(b), "l"(c)); return r;
}
__device__ __forceinline__ u64 add2(u64 a, u64 b) {
    u64 r; asm("add.rn.f32x2 %0, %1, %2;" : "=l"(r) : "l"(a), "l"(b)); return r;
}
__device__ __forceinline__ u64 mul2(u64 a, u64 b) {
    u64 r; asm("mul.rn.f32x2 %0, %1, %2;" : "=l"(r) : "l"(a), "l"(b)); return r;
}
#define PK2(c) pk((c), (c))

// Raw (unpacked) row data: aligned float4 per image + 2 halo scalars per image.
struct Raw {
    float4 vp, vt;
    float h0p, h5p, h0t, h5t;
};

__device__ __forceinline__ void fetch_raw(const float* __restrict__ P,
                                          const float* __restrict__ T,
                                          int y, int x0, bool hasL, bool hasR, Raw& rw) {
    if ((unsigned)y < (unsigned)Hd) {
        const float* rp = P + (y << 10) + x0;
        const float* rt = T + (y << 10) + x0;
        rw.vp = *reinterpret_cast<const float4*>(rp);
        rw.vt = *reinterpret_cast<const float4*>(rt);
        rw.h0p = hasL ? rp[-1] : 0.f;
        rw.h5p = hasR ? rp[4]  : 0.f;
        rw.h0t = hasL ? rt[-1] : 0.f;
        rw.h5t = hasR ? rt[4]  : 0.f;
    } else {
        rw.vp = make_float4(0.f, 0.f, 0.f, 0.f);
        rw.vt = make_float4(0.f, 0.f, 0.f, 0.f);
        rw.h0p = rw.h5p = rw.h0t = rw.h5t = 0.f;
    }
}

__device__ __forceinline__ void pack_raw(const Raw& rw, u64 out[6]) {
    out[0] = pk(rw.h0p,  rw.h0t);
    out[1] = pk(rw.vp.x, rw.vt.x);
    out[2] = pk(rw.vp.y, rw.vt.y);
    out[3] = pk(rw.vp.z, rw.vt.z);
    out[4] = pk(rw.vp.w, rw.vt.w);
    out[5] = pk(rw.h5p,  rw.h5t);
}

__global__ void __launch_bounds__(TPB, 2)
curv_loss_kernel(const float* __restrict__ pred, const float* __restrict__ target,
                 int nblocks, double invN, float* __restrict__ out) {
    const int x0 = threadIdx.x * QW;
    const int y0 = blockIdx.x * ROWS;
    const bool hasL = (x0 > 0);
    const bool hasR = (x0 + 4 < Wd);
    const size_t img_off = (size_t)blockIdx.y * (size_t)(Hd * Wd);
    const float* P = pred + img_off;
    const float* T = target + img_off;

    const u64 NEG1 = PK2(-1.f);
    const u64 TWO  = PK2(2.f);
    const u64 M2   = PK2(-2.f);
    const u64 ONE  = PK2(1.f);
    const u64 EPS2 = PK2(EPSV);
    const u64 C80  = PK2(1.f / 80.f);
    const u64 C3   = PK2(1.f / 3.f);   // r,t: /3 ( /100 deferred to weights )
    const u64 CH   = PK2(0.5f);        // "2s" term: raw/2 ( /100 deferred )
    #define SUB2(a, b) fma2((b), NEG1, (a))

    u64 ra[6], rb[6], rc[6];
    Raw rw;
    fetch_raw(P, T, y0 - 1, x0, hasL, hasR, rw); pack_raw(rw, ra);
    fetch_raw(P, T, y0,     x0, hasL, hasR, rw); pack_raw(rw, rb);
    fetch_raw(P, T, y0 + 1, x0, hasL, hasR, rw);   // prefetch for rr=0

    float sp = 0.f, sl = 0.f, sm = 0.f;

    #pragma unroll
    for (int rr = 0; rr < ROWS; rr++) {
        pack_raw(rw, rc);
        if (rr < ROWS - 1)
            fetch_raw(P, T, y0 + rr + 2, x0, hasL, hasR, rw);  // issue next loads early

        // shared column precomputes (6 cols serve 4 outputs)
        u64 v1, dd[6], w[6], cs[6], u[6];
        #pragma unroll
        for (int i = 0; i < 6; i++) {
            v1    = add2(ra[i], rc[i]);     // top+bottom
            dd[i] = SUB2(rc[i], ra[i]);     // bottom-top
            w[i]  = fma2(rb[i], TWO, v1);   // for p (sobel_x column)
            cs[i] = add2(v1, rb[i]);        // for r (k_xx column)
            u[i]  = fma2(rb[i], M2, v1);    // for t (k_yy column)
        }

        #pragma unroll
        for (int j = 0; j < 4; j++) {
            u64 p  = mul2(SUB2(w[j + 2], w[j]), C80);
            u64 q  = mul2(add2(fma2(dd[j + 1], TWO, dd[j]), dd[j + 2]), C80);
            u64 r  = mul2(add2(fma2(cs[j + 1], M2, cs[j]), cs[j + 2]), C3);
            u64 tt = mul2(add2(add2(u[j], u[j + 1]), u[j + 2]), C3);
            u64 s  = mul2(SUB2(dd[j], dd[j + 2]), CH);   // == 100*(2*s_true)

            u64 p2 = mul2(p, p), q2 = mul2(q, q), pq = mul2(p, q);
            u64 d  = add2(p2, q2);
            u64 onepd = add2(d, ONE);

            float dl, dh, ol, oh;
            unpk(d, dl, dh); unpk(onepd, ol, oh);
            float rsl = f_rsqrt(ol), rsh = f_rsqrt(oh);
            float sdl = f_sqrt(dl),  sdh = f_sqrt(dh);
            u64 rs1 = pk(rsl, rsh);
            u64 sqd = pk(sdl, sdh);

            u64 sq1 = mul2(onepd, rs1);          // sqrt(1+d)
            u64 A = fma2(d, sq1, EPS2);          // d*sqrt(1+d)+eps
            u64 B = fma2(d, sqd, EPS2);          // d^1.5+eps
            u64 AB = mul2(A, B);
            float abl, abh; unpk(AB, abl, abh);
            u64 ip = pk(f_rcp(abl), f_rcp(abh)); // 1/(A*B)
            u64 invA = mul2(ip, B);
            u64 invB = mul2(ip, A);
            u64 rs2  = mul2(rs1, rs1);
            u64 invC = mul2(rs2, rs1);           // (1+d)^-1.5  (x0.5 deferred)

            u64 rp2 = mul2(r, p2), tq2 = mul2(tt, q2);
            u64 rq2 = mul2(r, q2), tp2 = mul2(tt, p2);
            u64 s2pq = mul2(s, pq);
            u64 n1   = add2(add2(rp2, s2pq), tq2);
            u64 core = SUB2(add2(rq2, tp2), s2pq);   // = planform numerator
            u64 n3   = add2(add2(r, tt), core);      // mean numerator

            u64 prof = mul2(n1, invA);
            u64 plan = mul2(core, invB);
            u64 mn   = mul2(n3, invC);

            bool fl = (dl < EPSV), fh = (dh < EPSV);
            float a0, a1;
            unpk(prof, a0, a1);
            if (fl) a0 = 0.f; if (fh) a1 = 0.f;
            sp += fabsf(a0 - a1);
            unpk(plan, a0, a1);
            if (fl) a0 = 0.f; if (fh) a1 = 0.f;
            sl += fabsf(a0 - a1);
            unpk(mn, a0, a1);
            sm += fabsf(a0 - a1);
        }

        #pragma unroll
        for (int i = 0; i < 6; i++) { ra[i] = rb[i]; rb[i] = rc[i]; }
    }

    // ── deterministic block reduction ──────────────────────────────────
    #pragma unroll
    for (int off = 16; off > 0; off >>= 1) {
        sp += __shfl_xor_sync(0xFFFFFFFFu, sp, off);
        sl += __shfl_xor_sync(0xFFFFFFFFu, sl, off);
        sm += __shfl_xor_sync(0xFFFFFFFFu, sm, off);
    }
    __shared__ float sh[TPB / 32][3];
    __shared__ bool islast;
    int wid = threadIdx.x >> 5, lid = threadIdx.x & 31;
    if (lid == 0) { sh[wid][0] = sp; sh[wid][1] = sl; sh[wid][2] = sm; }
    __syncthreads();
    if (threadIdx.x == 0) {
        float a = 0.f, b = 0.f, c = 0.f;
        #pragma unroll
        for (int i = 0; i < TPB / 32; i++) { a += sh[i][0]; b += sh[i][1]; c += sh[i][2]; }
        int bid = blockIdx.y * gridDim.x + blockIdx.x;
        // weights: (0.5, 0.3, 0.2*0.5) ; global 1/100 folded into invN
        g_partials[bid] = 0.5f * a + 0.3f * b + 0.1f * c;
        __threadfence();
        unsigned prev = atomicAdd(&g_count, 1u);
        islast = (prev == (unsigned)(nblocks - 1));
    }
    __syncthreads();

    if (islast) {
        __threadfence();
        __shared__ double shd[TPB];
        double acc = 0.0;
        for (int i = threadIdx.x; i < nblocks; i += TPB)
            acc += (double)g_partials[i];
        shd[threadIdx.x] = acc;
        __syncthreads();
        for (int off = TPB / 2; off > 0; off >>= 1) {
            if (threadIdx.x < off) shd[threadIdx.x] += shd[threadIdx.x + off];
            __syncthreads();
        }
        if (threadIdx.x == 0) {
            out[0] = (float)(shd[0] * invN);
            g_count = 0;   // reset for graph replay
        }
    }
}

extern "C" void kernel_launch(void* const* d_in, const int* in_sizes, int n_in,
                              void* d_out, int out_size) {
    const float* pred   = (const float*)d_in[0];
    const float* target = (const float*)d_in[1];
    float* out = (float*)d_out;

    int B = in_sizes[0] / (Hd * Wd);
    if (B < 1) B = 1;

    dim3 grid(Hd / ROWS, B);
    int nblocks = (Hd / ROWS) * B;
    double invN = 0.01 / ((double)B * Hd * Wd);   // 1/100 scale deferral folded here
    curv_loss_kernel<<<grid, TPB>>>(pred, target, nblocks, invN, out);
}